// round 13
// baseline (speedup 1.0000x reference)
#include <cuda_runtime.h>
#include <cuda_bf16.h>
#include <cuda_fp16.h>
#include <cstdint>

// ============================================================================
// VQVAE quantization: fp16 mma.sync GEMM + top-2 margin + exact fp32 rescue.
//   laten   : (B=32, D=64, H=32, W=32) fp32
//   codebook: (K=2048, D=64) fp32
// Output (fp32): [ idx (32768) | quant (2097152, channel-first) ]
// Approx distances via fp16 GEMM (err std ~3e-3); any point whose top-2 gap
// < MARGIN is re-resolved exactly in fp32, making the argmin fp32-exact.
// ============================================================================

#define NB 32
#define ND 64
#define NH 32
#define NW 32
#define NK 2048
#define HW (NH * NW)                  // 1024
#define N_POINTS (NB * HW)            // 32768
#define N_QUANT  (NB * ND * HW)       // 2097152
#define TM 128                        // points per CTA
#define TN 64                         // codes per N-tile
#define NTILES (NK / TN)              // 32
#define ROWB 144                      // smem row: 128B data + 16B pad (9%8==1)
#define BUFB (TN * ROWB)              // 9216 per B buffer
#define MARGIN 0.12f

// smem layout (bytes)
#define SM_A    0                     // 128 * 144 = 18432
#define SM_B    18432                 // 2 * 9216 = 18432
#define SM_ESQ  36864                 // 2048 * 4 = 8192
#define SM_SIZE 45056

// ---- device scratch ---------------------------------------------------------
__device__ __align__(16) __half g_B[NK * ND];   // fp16 codebook, 256 KB
__device__ __align__(16) float g_esq[NK];
__device__ int g_rescan[N_POINTS];
__device__ int g_rcount;

// ---- helpers ----------------------------------------------------------------
__device__ __forceinline__ uint32_t smem_u32(const void* p) {
    uint32_t a;
    asm("{ .reg .u64 t; cvta.to.shared.u64 t, %1; cvt.u32.u64 %0, t; }"
        : "=r"(a) : "l"(p));
    return a;
}
#define CP_ASYNC16(s, g) \
    asm volatile("cp.async.cg.shared.global [%0], [%1], 16;" :: "r"(s), "l"(g))
#define CP_COMMIT() asm volatile("cp.async.commit_group;" ::: "memory")
#define CP_WAIT(n)  asm volatile("cp.async.wait_group %0;" :: "n"(n) : "memory")

#define LDSM_X4(r0, r1, r2, r3, a)                                             \
    asm volatile("ldmatrix.sync.aligned.m8n8.x4.shared.b16 {%0,%1,%2,%3}, [%4];" \
                 : "=r"(r0), "=r"(r1), "=r"(r2), "=r"(r3) : "r"(a))

#define MMA_F16(c, a, b0, b1)                                                  \
    asm volatile("mma.sync.aligned.m16n8k16.row.col.f32.f16.f16.f32 "          \
                 "{%0,%1,%2,%3}, {%4,%5,%6,%7}, {%8,%9}, {%0,%1,%2,%3};"       \
                 : "+f"((c)[0]), "+f"((c)[1]), "+f"((c)[2]), "+f"((c)[3])      \
                 : "r"((a)[0]), "r"((a)[1]), "r"((a)[2]), "r"((a)[3]),         \
                   "r"(b0), "r"(b1))

// ---- kernel: build fp16 B + exact esq (+ zero rescan counter) ---------------
// 4 threads per code, each handles 16 dims; esq reduced across the quad.
__global__ void __launch_bounds__(256)
build_B_kernel(const float* __restrict__ codebook) {
    int q = blockIdx.x * 256 + threadIdx.x;
    if (q == 0) g_rcount = 0;
    int k = q >> 2, part = q & 3;
    if (k >= NK) return;
    const float4* src = (const float4*)(codebook + k * ND + part * 16);
    __half2 h2[8];
    float s = 0.f;
#pragma unroll
    for (int i = 0; i < 4; i++) {
        float4 v = src[i];
        s += v.x * v.x + v.y * v.y + v.z * v.z + v.w * v.w;
        h2[2 * i + 0] = __floats2half2_rn(v.x, v.y);
        h2[2 * i + 1] = __floats2half2_rn(v.z, v.w);
    }
    s += __shfl_xor_sync(0xffffffffu, s, 1);
    s += __shfl_xor_sync(0xffffffffu, s, 2);
    uint4* dst = (uint4*)(g_B + (size_t)k * ND + part * 16);
    dst[0] = *(uint4*)&h2[0];
    dst[1] = *(uint4*)&h2[4];
    if (part == 0) g_esq[k] = s;
}

// ---- main kernel: A-convert + fp16 GEMM + top-2 argmin + fused finalize ----
__global__ void __launch_bounds__(256, 2)
gemm_argmin_kernel(const float* __restrict__ laten,
                   const float* __restrict__ codebook,
                   float* __restrict__ out, int mode, int idx_off) {
    extern __shared__ char smem[];
    const uint32_t sb = smem_u32(smem);
    const int tid  = threadIdx.x;
    const int lane = tid & 31;
    const int wid  = tid >> 5;
    const int warp_m = (wid & 3) * 32;   // 4 m-warps
    const int warp_n = (wid >> 2) * 32;  // 2 n-warps

    const int n0  = blockIdx.x * TM;
    const int b   = n0 >> 10;
    const int hw0 = n0 & (HW - 1);

    // -- prologue: B tiles 0,1 via cp.async (2 groups) --
#pragma unroll 1
    for (int t = 0; t < 2; t++) {
        const char* gsrc = (const char*)(g_B + (size_t)t * TN * ND);
#pragma unroll
        for (int i = tid; i < TN * 8; i += 256) {
            int row = i >> 3, c = i & 7;
            CP_ASYNC16(sb + SM_B + t * BUFB + row * ROWB + c * 16,
                       gsrc + row * 128 + c * 16);
        }
        CP_COMMIT();
    }

    // -- A convert: laten -> fp16 rows in smem --
    {
        const int p  = tid & 127;
        const int db = tid >> 7;
        const float* lp = laten + (size_t)b * (ND * HW) + hw0 + p;
#pragma unroll
        for (int i = 0; i < 32; i++) {
            int d = 2 * i + db;
            *(unsigned short*)(smem + SM_A + p * ROWB + d * 2) =
                __half_as_ushort(__float2half_rn(lp[d * HW]));
        }
    }
    // -- esq -> smem --
#pragma unroll
    for (int i = tid; i < NK / 4; i += 256)
        ((float4*)(smem + SM_ESQ))[i] = ((const float4*)g_esq)[i];

    __syncthreads();   // A stage + esq visible

    // ldmatrix lane base addresses
    const uint32_t a_base = sb + SM_A
        + (uint32_t)(warp_m + ((lane >> 3) & 1) * 8 + (lane & 7)) * ROWB
        + (uint32_t)(lane >> 4) * 16;
    const uint32_t b_base = sb + SM_B
        + (uint32_t)(warp_n + (lane >> 4) * 8 + (lane & 7)) * ROWB
        + (uint32_t)((lane >> 3) & 1) * 16;

    // -- hoist A fragments for the whole tile loop (invariant) --
    uint32_t axh[4][2][4];
#pragma unroll
    for (int ks = 0; ks < 4; ks++) {
#pragma unroll
        for (int mi = 0; mi < 2; mi++)
            LDSM_X4(axh[ks][mi][0], axh[ks][mi][1], axh[ks][mi][2],
                    axh[ks][mi][3], a_base + mi * 16 * ROWB + ks * 32);
    }

    CP_WAIT(1);
    __syncthreads();   // B tile 0 visible

    // top-2 state: 4 row-slots (mi*2 + rowhalf)
    float b1v[4] = {3.4e38f, 3.4e38f, 3.4e38f, 3.4e38f};
    float b2v[4] = {3.4e38f, 3.4e38f, 3.4e38f, 3.4e38f};
    int   bkv[4] = {0, 0, 0, 0};

#pragma unroll 1
    for (int nt = 0; nt < NTILES; nt++) {
        const uint32_t bB = b_base + (nt & 1) * BUFB;
        float acc[2][4][4];
#pragma unroll
        for (int mi = 0; mi < 2; mi++)
#pragma unroll
            for (int ni = 0; ni < 4; ni++)
#pragma unroll
                for (int q = 0; q < 4; q++) acc[mi][ni][q] = 0.f;

#pragma unroll
        for (int ks = 0; ks < 4; ks++) {
            uint32_t bh0[4], bh1[4];
            LDSM_X4(bh0[0], bh0[1], bh0[2], bh0[3], bB + ks * 32);
            LDSM_X4(bh1[0], bh1[1], bh1[2], bh1[3], bB + 16 * ROWB + ks * 32);
            MMA_F16(acc[0][0], axh[ks][0], bh0[0], bh0[1]);
            MMA_F16(acc[0][1], axh[ks][0], bh0[2], bh0[3]);
            MMA_F16(acc[0][2], axh[ks][0], bh1[0], bh1[1]);
            MMA_F16(acc[0][3], axh[ks][0], bh1[2], bh1[3]);
            MMA_F16(acc[1][0], axh[ks][1], bh0[0], bh0[1]);
            MMA_F16(acc[1][1], axh[ks][1], bh0[2], bh0[3]);
            MMA_F16(acc[1][2], axh[ks][1], bh1[0], bh1[1]);
            MMA_F16(acc[1][3], axh[ks][1], bh1[2], bh1[3]);
        }

        // epilogue: score = esq - 2*dot, track top-2 per row-slot
        const float* es = (const float*)(smem + SM_ESQ) + nt * TN + warp_n;
#pragma unroll
        for (int ni = 0; ni < 4; ni++) {
            int cb = ni * 8 + 2 * (lane & 3);
            float2 ev = *(const float2*)(es + cb);
            int colg = nt * TN + warp_n + cb;
#pragma unroll
            for (int mi = 0; mi < 2; mi++)
#pragma unroll
                for (int h = 0; h < 2; h++) {
                    int slot = mi * 2 + h;
                    float s0 = fmaf(-2.f, acc[mi][ni][2 * h + 0], ev.x);
                    float s1 = fmaf(-2.f, acc[mi][ni][2 * h + 1], ev.y);
                    if (s0 < b1v[slot]) {
                        b2v[slot] = b1v[slot]; b1v[slot] = s0; bkv[slot] = colg;
                    } else if (s0 < b2v[slot]) b2v[slot] = s0;
                    if (s1 < b1v[slot]) {
                        b2v[slot] = b1v[slot]; b1v[slot] = s1; bkv[slot] = colg + 1;
                    } else if (s1 < b2v[slot]) b2v[slot] = s1;
                }
        }

        __syncthreads();            // all warps done reading buf (nt&1)
        if (nt + 2 < NTILES) {      // refill it with tile nt+2
            const char* gsrc = (const char*)(g_B + (size_t)(nt + 2) * TN * ND);
#pragma unroll
            for (int i = tid; i < TN * 8; i += 256) {
                int row = i >> 3, c = i & 7;
                CP_ASYNC16(sb + SM_B + (nt & 1) * BUFB + row * ROWB + c * 16,
                           gsrc + row * 128 + c * 16);
            }
            CP_COMMIT();
            CP_WAIT(1);             // tile nt+1 complete
        } else {
            CP_WAIT(0);
        }
        __syncthreads();
    }

    // -- merge 1: across the 4 lanes sharing each accumulator row ------------
#pragma unroll
    for (int slot = 0; slot < 4; slot++) {
#pragma unroll
        for (int m = 1; m <= 2; m <<= 1) {
            float o1 = __shfl_xor_sync(0xffffffffu, b1v[slot], m);
            float o2 = __shfl_xor_sync(0xffffffffu, b2v[slot], m);
            int   ok = __shfl_xor_sync(0xffffffffu, bkv[slot], m);
            float nb2 = fminf(fmaxf(b1v[slot], o1), fminf(b2v[slot], o2));
            if (o1 < b1v[slot]) { b1v[slot] = o1; bkv[slot] = ok; }
            b2v[slot] = nb2;
        }
    }

    // -- merge 2: across the two n-warp groups; B smem is dead now -----------
    float* cmb = (float*)(smem + SM_B);   // [TM][4]
    if (warp_n == 32 && (lane & 3) == 0) {
#pragma unroll
        for (int slot = 0; slot < 4; slot++) {
            int mi = slot >> 1, h = slot & 1;
            int row = warp_m + mi * 16 + h * 8 + (lane >> 2);
            cmb[row * 4 + 0] = b1v[slot];
            cmb[row * 4 + 1] = b2v[slot];
            ((int*)cmb)[row * 4 + 2] = bkv[slot];
        }
    }
    __syncthreads();
    if (warp_n == 0 && (lane & 3) == 0) {
#pragma unroll
        for (int slot = 0; slot < 4; slot++) {
            int mi = slot >> 1, h = slot & 1;
            int row = warp_m + mi * 16 + h * 8 + (lane >> 2);
            float o1 = cmb[row * 4 + 0];
            float o2 = cmb[row * 4 + 1];
            int   ok = ((int*)cmb)[row * 4 + 2];
            float m2 = fminf(fmaxf(b1v[slot], o1), fminf(b2v[slot], o2));
            int   mk = (b1v[slot] <= o1) ? bkv[slot] : ok;
            float m1 = fminf(b1v[slot], o1);
            cmb[row * 4 + 0] = m1;
            cmb[row * 4 + 1] = m2;
            ((int*)cmb)[row * 4 + 2] = mk;
        }
    }
    __syncthreads();

    // -- fused finalize: 128 threads, one point each --------------------------
    if (tid < TM) {
        float b1 = cmb[tid * 4 + 0];
        float b2 = cmb[tid * 4 + 1];
        int   bk = ((int*)cmb)[tid * 4 + 2];
        int n = n0 + tid;
        bool resc = (b2 - b1 < MARGIN);
        unsigned msk = __ballot_sync(0xffffffffu, resc);
        if (resc) {
            int ldr = __ffs(msk) - 1;
            int base = 0;
            if (lane == ldr) base = atomicAdd(&g_rcount, __popc(msk));
            base = __shfl_sync(msk, base, ldr);
            g_rescan[base + __popc(msk & ((1u << lane) - 1u))] = n;
        } else {
            if (mode & 1) out[n] = (float)bk;
            if (mode & 2) {
                int hw = n & (HW - 1);
                float* oq = out + idx_off + (size_t)b * (ND * HW) + hw;
                const float* cb = codebook + bk * ND;
#pragma unroll
                for (int d = 0; d < ND; d++) oq[d * HW] = __ldg(&cb[d]);
            }
        }
    }
}

// ---- exact fp32 rescan for near-ties ---------------------------------------
__global__ void __launch_bounds__(256)
rescan_kernel(const float* __restrict__ laten, const float* __restrict__ codebook,
              float* __restrict__ out, int mode, int idx_off) {
    __shared__ float sx[ND];
    __shared__ float sv[256];
    __shared__ int si[256];
    int tid = threadIdx.x;
    int cnt = g_rcount;
    for (int ii = blockIdx.x; ii < cnt; ii += gridDim.x) {
        int n = g_rescan[ii];
        int b = n >> 10, hw = n & (HW - 1);
        if (tid < ND) sx[tid] = laten[(size_t)b * (ND * HW) + tid * HW + hw];
        __syncthreads();
        float best = 3.4e38f;
        int bi = 0;
        for (int k = tid; k < NK; k += 256) {
            const float4* c = (const float4*)(codebook + k * ND);
            float a0 = 0.f, a1 = 0.f, a2 = 0.f, a3 = 0.f;
#pragma unroll
            for (int i = 0; i < ND / 4; i++) {
                float4 v = c[i];
                a0 = fmaf(sx[4 * i + 0], v.x, a0);
                a1 = fmaf(sx[4 * i + 1], v.y, a1);
                a2 = fmaf(sx[4 * i + 2], v.z, a2);
                a3 = fmaf(sx[4 * i + 3], v.w, a3);
            }
            float s = fmaf(-2.f, (a0 + a1) + (a2 + a3), g_esq[k]);
            if (s < best) { best = s; bi = k; }
        }
        sv[tid] = best;
        si[tid] = bi;
        __syncthreads();
        for (int off = 128; off; off >>= 1) {
            if (tid < off) {
                float ov = sv[tid + off];
                int oi = si[tid + off];
                if (ov < sv[tid] || (ov == sv[tid] && oi < si[tid])) {
                    sv[tid] = ov;
                    si[tid] = oi;
                }
            }
            __syncthreads();
        }
        int bk = si[0];
        if ((mode & 1) && tid == 0) out[n] = (float)bk;
        if ((mode & 2) && tid < ND)
            out[idx_off + (size_t)b * (ND * HW) + tid * HW + hw] =
                codebook[bk * ND + tid];
        __syncthreads();
    }
}

// ---- host launcher ----------------------------------------------------------
extern "C" void kernel_launch(void* const* d_in, const int* in_sizes, int n_in,
                              void* d_out, int out_size) {
    const float* laten    = (const float*)d_in[0];
    const float* codebook = (const float*)d_in[1];
    float* out = (float*)d_out;

    int mode, idx_off;
    if (out_size == N_POINTS + N_QUANT) { mode = 3; idx_off = N_POINTS; }
    else if (out_size == N_QUANT)       { mode = 2; idx_off = 0;        }
    else                                { mode = 1; idx_off = 0;        }

    cudaFuncSetAttribute(gemm_argmin_kernel,
                         cudaFuncAttributeMaxDynamicSharedMemorySize, SM_SIZE);

    build_B_kernel<<<NK * 4 / 256, 256>>>(codebook);
    gemm_argmin_kernel<<<N_POINTS / TM, 256, SM_SIZE>>>(laten, codebook, out,
                                                        mode, idx_off);
    rescan_kernel<<<256, 256>>>(laten, codebook, out, mode, idx_off);
}

// round 15
// speedup vs baseline: 1.5696x; 1.5696x over previous
#include <cuda_runtime.h>
#include <cuda_bf16.h>
#include <cuda_fp16.h>
#include <cstdint>

// ============================================================================
// VQVAE quantization: fp16 mma.sync GEMM + top-2 margin + exact fp32 rescue.
//   laten   : (B=32, D=64, H=32, W=32) fp32
//   codebook: (K=2048, D=64) fp32
// Output (fp32): [ idx (32768) | quant (2097152, channel-first) ]
// Approx distances via fp16 GEMM (score err std ~5e-3); any point whose
// top-2 gap < MARGIN (9 sigma) is re-resolved exactly in fp32.
// ============================================================================

#define NB 32
#define ND 64
#define NH 32
#define NW 32
#define NK 2048
#define HW (NH * NW)                  // 1024
#define N_POINTS (NB * HW)            // 32768
#define N_QUANT  (NB * ND * HW)       // 2097152
#define TM 128                        // points per CTA
#define TI 128                        // codes per pipeline iteration
#define NITER (NK / TI)               // 16
#define ROWB 144                      // smem row: 128B data + 16B pad (9%8==1)
#define BUFB (TI * ROWB)              // 18432 per B buffer (128 rows)
#define MARGIN 0.045f

// smem layout (bytes)
#define SM_A    0                     // 128 * 144 = 18432
#define SM_B    18432                 // 3 * 18432 = 55296
#define SM_ESQ  73728                 // 2048 * 4 = 8192
#define SM_SIZE 81920

// ---- device scratch ---------------------------------------------------------
__device__ __align__(16) __half g_B[NK * ND];   // fp16 codebook, 256 KB
__device__ __align__(16) float g_esq[NK];
__device__ int g_rescan[N_POINTS];
__device__ int g_rcount;

// ---- helpers ----------------------------------------------------------------
__device__ __forceinline__ uint32_t smem_u32(const void* p) {
    uint32_t a;
    asm("{ .reg .u64 t; cvta.to.shared.u64 t, %1; cvt.u32.u64 %0, t; }"
        : "=r"(a) : "l"(p));
    return a;
}
#define CP_ASYNC16(s, g) \
    asm volatile("cp.async.cg.shared.global [%0], [%1], 16;" :: "r"(s), "l"(g))
#define CP_COMMIT() asm volatile("cp.async.commit_group;" ::: "memory")
#define CP_WAIT(n)  asm volatile("cp.async.wait_group %0;" :: "n"(n) : "memory")

#define LDSM_X4(r0, r1, r2, r3, a)                                             \
    asm volatile("ldmatrix.sync.aligned.m8n8.x4.shared.b16 {%0,%1,%2,%3}, [%4];" \
                 : "=r"(r0), "=r"(r1), "=r"(r2), "=r"(r3) : "r"(a))

#define MMA_F16(c, a, b0, b1)                                                  \
    asm volatile("mma.sync.aligned.m16n8k16.row.col.f32.f16.f16.f32 "          \
                 "{%0,%1,%2,%3}, {%4,%5,%6,%7}, {%8,%9}, {%0,%1,%2,%3};"       \
                 : "+f"((c)[0]), "+f"((c)[1]), "+f"((c)[2]), "+f"((c)[3])      \
                 : "r"((a)[0]), "r"((a)[1]), "r"((a)[2]), "r"((a)[3]),         \
                   "r"(b0), "r"(b1))

// ---- kernel: build fp16 B + exact esq (+ zero rescan counter) ---------------
__global__ void __launch_bounds__(256)
build_B_kernel(const float* __restrict__ codebook) {
    int q = blockIdx.x * 256 + threadIdx.x;
    if (q == 0) g_rcount = 0;
    int k = q >> 2, part = q & 3;
    if (k >= NK) return;
    const float4* src = (const float4*)(codebook + k * ND + part * 16);
    __half2 h2[8];
    float s = 0.f;
#pragma unroll
    for (int i = 0; i < 4; i++) {
        float4 v = src[i];
        s += v.x * v.x + v.y * v.y + v.z * v.z + v.w * v.w;
        h2[2 * i + 0] = __floats2half2_rn(v.x, v.y);
        h2[2 * i + 1] = __floats2half2_rn(v.z, v.w);
    }
    s += __shfl_xor_sync(0xffffffffu, s, 1);
    s += __shfl_xor_sync(0xffffffffu, s, 2);
    uint4* dst = (uint4*)(g_B + (size_t)k * ND + part * 16);
    dst[0] = *(uint4*)&h2[0];
    dst[1] = *(uint4*)&h2[4];
    if (part == 0) g_esq[k] = s;
}

// load one 128-code iteration buffer (1024 x 16B chunks, 4 per thread)
__device__ __forceinline__ void load_iter(uint32_t sb, int buf, int it, int tid) {
    const char* gsrc = (const char*)(g_B + (size_t)it * TI * ND);
    uint32_t dst = sb + SM_B + buf * BUFB;
#pragma unroll
    for (int i = tid; i < TI * 8; i += 256) {
        int row = i >> 3, c = i & 7;
        CP_ASYNC16(dst + row * ROWB + c * 16, gsrc + row * 128 + c * 16);
    }
    CP_COMMIT();
}

// ---- main kernel: A-convert + fp16 GEMM + top-2 argmin + fused finalize ----
__global__ void __launch_bounds__(256, 2)
gemm_argmin_kernel(const float* __restrict__ laten,
                   const float* __restrict__ codebook,
                   float* __restrict__ out, int mode, int idx_off) {
    extern __shared__ char smem[];
    const uint32_t sb = smem_u32(smem);
    const int tid  = threadIdx.x;
    const int lane = tid & 31;
    const int wid  = tid >> 5;
    const int warp_m = (wid & 3) * 32;   // 4 m-warps
    const int warp_n = (wid >> 2) * 32;  // 2 n-warps (cols within 64-code sub-tile)

    const int n0  = blockIdx.x * TM;
    const int b   = n0 >> 10;
    const int hw0 = n0 & (HW - 1);

    // -- prologue: iteration buffers 0,1 --
    load_iter(sb, 0, 0, tid);
    load_iter(sb, 1, 1, tid);

    // -- A convert: laten -> fp16 rows in smem --
    {
        const int p  = tid & 127;
        const int db = tid >> 7;
        const float* lp = laten + (size_t)b * (ND * HW) + hw0 + p;
#pragma unroll
        for (int i = 0; i < 32; i++) {
            int d = 2 * i + db;
            *(unsigned short*)(smem + SM_A + p * ROWB + d * 2) =
                __half_as_ushort(__float2half_rn(lp[d * HW]));
        }
    }
    // -- esq -> smem --
#pragma unroll
    for (int i = tid; i < NK / 4; i += 256)
        ((float4*)(smem + SM_ESQ))[i] = ((const float4*)g_esq)[i];

    __syncthreads();   // A stage + esq visible

    // ldmatrix lane base addresses
    const uint32_t a_base = sb + SM_A
        + (uint32_t)(warp_m + ((lane >> 3) & 1) * 8 + (lane & 7)) * ROWB
        + (uint32_t)(lane >> 4) * 16;
    const uint32_t b_lane = (uint32_t)(warp_n + (lane >> 4) * 8 + (lane & 7)) * ROWB
        + (uint32_t)((lane >> 3) & 1) * 16;

    // -- hoist A fragments for the whole loop (invariant) --
    uint32_t axh[4][2][4];
#pragma unroll
    for (int ks = 0; ks < 4; ks++) {
#pragma unroll
        for (int mi = 0; mi < 2; mi++)
            LDSM_X4(axh[ks][mi][0], axh[ks][mi][1], axh[ks][mi][2],
                    axh[ks][mi][3], a_base + mi * 16 * ROWB + ks * 32);
    }

    // top-2 state: 4 row-slots (mi*2 + rowhalf)
    float b1v[4] = {3.4e38f, 3.4e38f, 3.4e38f, 3.4e38f};
    float b2v[4] = {3.4e38f, 3.4e38f, 3.4e38f, 3.4e38f};
    int   bkv[4] = {0, 0, 0, 0};

#pragma unroll 1
    for (int it = 0; it < NITER; it++) {
        if (it == NITER - 1) { CP_WAIT(0); } else { CP_WAIT(1); }
        __syncthreads();   // buffer it%3 ready for ALL threads; buffer
                           // (it+2)%3 fully consumed by ALL threads (iter it-1)

        const uint32_t bufB = sb + SM_B + (it % 3) * BUFB + b_lane;

        // two 64-code sub-tiles
#pragma unroll
        for (int sub = 0; sub < 2; sub++) {
            const uint32_t bB = bufB + sub * (64 * ROWB);
            float acc[2][4][4];
#pragma unroll
            for (int mi = 0; mi < 2; mi++)
#pragma unroll
                for (int ni = 0; ni < 4; ni++)
#pragma unroll
                    for (int q = 0; q < 4; q++) acc[mi][ni][q] = 0.f;

#pragma unroll
            for (int ks = 0; ks < 4; ks++) {
                uint32_t bh0[4], bh1[4];
                LDSM_X4(bh0[0], bh0[1], bh0[2], bh0[3], bB + ks * 32);
                LDSM_X4(bh1[0], bh1[1], bh1[2], bh1[3], bB + 16 * ROWB + ks * 32);
                MMA_F16(acc[0][0], axh[ks][0], bh0[0], bh0[1]);
                MMA_F16(acc[0][1], axh[ks][0], bh0[2], bh0[3]);
                MMA_F16(acc[0][2], axh[ks][0], bh1[0], bh1[1]);
                MMA_F16(acc[0][3], axh[ks][0], bh1[2], bh1[3]);
                MMA_F16(acc[1][0], axh[ks][1], bh0[0], bh0[1]);
                MMA_F16(acc[1][1], axh[ks][1], bh0[2], bh0[3]);
                MMA_F16(acc[1][2], axh[ks][1], bh1[0], bh1[1]);
                MMA_F16(acc[1][3], axh[ks][1], bh1[2], bh1[3]);
            }

            // epilogue: score = esq - 2*dot, top-2 per row-slot
            const int kb0 = it * TI + sub * 64 + warp_n;
            const float* es = (const float*)(smem + SM_ESQ) + kb0;
#pragma unroll
            for (int ni = 0; ni < 4; ni++) {
                int cb = ni * 8 + 2 * (lane & 3);
                float2 ev = *(const float2*)(es + cb);
                int colg = kb0 + cb;
#pragma unroll
                for (int mi = 0; mi < 2; mi++)
#pragma unroll
                    for (int h = 0; h < 2; h++) {
                        int slot = mi * 2 + h;
                        float s0 = fmaf(-2.f, acc[mi][ni][2 * h + 0], ev.x);
                        float s1 = fmaf(-2.f, acc[mi][ni][2 * h + 1], ev.y);
                        if (s0 < b1v[slot]) {
                            b2v[slot] = b1v[slot]; b1v[slot] = s0;
                            bkv[slot] = colg;
                        } else if (s0 < b2v[slot]) b2v[slot] = s0;
                        if (s1 < b1v[slot]) {
                            b2v[slot] = b1v[slot]; b1v[slot] = s1;
                            bkv[slot] = colg + 1;
                        } else if (s1 < b2v[slot]) b2v[slot] = s1;
                    }
            }
        }

        // prefetch iteration it+2 into buffer (it+2)%3 — safe: that buffer
        // was consumed at iter it-1, and every thread passed this iter's
        // barrier (hence finished iter it-1) before we rewrite it.
        if (it + 2 < NITER) load_iter(sb, (it + 2) % 3, it + 2, tid);
    }
    __syncthreads();

    // -- merge 1: across the 4 lanes sharing each accumulator row ------------
#pragma unroll
    for (int slot = 0; slot < 4; slot++) {
#pragma unroll
        for (int m = 1; m <= 2; m <<= 1) {
            float o1 = __shfl_xor_sync(0xffffffffu, b1v[slot], m);
            float o2 = __shfl_xor_sync(0xffffffffu, b2v[slot], m);
            int   ok = __shfl_xor_sync(0xffffffffu, bkv[slot], m);
            float nb2 = fminf(fmaxf(b1v[slot], o1), fminf(b2v[slot], o2));
            if (o1 < b1v[slot]) { b1v[slot] = o1; bkv[slot] = ok; }
            b2v[slot] = nb2;
        }
    }

    // -- merge 2: across the two n-warp groups; B smem is dead now -----------
    float* cmb = (float*)(smem + SM_B);   // [TM][4]
    if (warp_n == 32 && (lane & 3) == 0) {
#pragma unroll
        for (int slot = 0; slot < 4; slot++) {
            int mi = slot >> 1, h = slot & 1;
            int row = warp_m + mi * 16 + h * 8 + (lane >> 2);
            cmb[row * 4 + 0] = b1v[slot];
            cmb[row * 4 + 1] = b2v[slot];
            ((int*)cmb)[row * 4 + 2] = bkv[slot];
        }
    }
    __syncthreads();
    if (warp_n == 0 && (lane & 3) == 0) {
#pragma unroll
        for (int slot = 0; slot < 4; slot++) {
            int mi = slot >> 1, h = slot & 1;
            int row = warp_m + mi * 16 + h * 8 + (lane >> 2);
            float o1 = cmb[row * 4 + 0];
            float o2 = cmb[row * 4 + 1];
            int   ok = ((int*)cmb)[row * 4 + 2];
            float m2 = fminf(fmaxf(b1v[slot], o1), fminf(b2v[slot], o2));
            int   mk = (b1v[slot] <= o1) ? bkv[slot] : ok;
            float m1 = fminf(b1v[slot], o1);
            cmb[row * 4 + 0] = m1;
            cmb[row * 4 + 1] = m2;
            ((int*)cmb)[row * 4 + 2] = mk;
        }
    }
    __syncthreads();

    // -- fused finalize: 128 threads, one point each --------------------------
    if (tid < TM) {
        float b1 = cmb[tid * 4 + 0];
        float b2 = cmb[tid * 4 + 1];
        int   bk = ((int*)cmb)[tid * 4 + 2];
        int n = n0 + tid;
        bool resc = (b2 - b1 < MARGIN);
        unsigned msk = __ballot_sync(0xffffffffu, resc);
        if (resc) {
            int ldr = __ffs(msk) - 1;
            int base = 0;
            if (lane == ldr) base = atomicAdd(&g_rcount, __popc(msk));
            base = __shfl_sync(msk, base, ldr);
            g_rescan[base + __popc(msk & ((1u << lane) - 1u))] = n;
        } else {
            if (mode & 1) out[n] = (float)bk;
            if (mode & 2) {
                int hw = n & (HW - 1);
                float* oq = out + idx_off + (size_t)b * (ND * HW) + hw;
                const float* cb = codebook + bk * ND;
#pragma unroll
                for (int d = 0; d < ND; d++) oq[d * HW] = __ldg(&cb[d]);
            }
        }
    }
}

// ---- exact fp32 rescan for near-ties ---------------------------------------
__global__ void __launch_bounds__(256)
rescan_kernel(const float* __restrict__ laten, const float* __restrict__ codebook,
              float* __restrict__ out, int mode, int idx_off) {
    __shared__ float sx[ND];
    __shared__ float sv[256];
    __shared__ int si[256];
    int tid = threadIdx.x;
    int cnt = g_rcount;
    for (int ii = blockIdx.x; ii < cnt; ii += gridDim.x) {
        int n = g_rescan[ii];
        int b = n >> 10, hw = n & (HW - 1);
        if (tid < ND) sx[tid] = laten[(size_t)b * (ND * HW) + tid * HW + hw];
        __syncthreads();
        float best = 3.4e38f;
        int bi = 0;
        for (int k = tid; k < NK; k += 256) {
            const float4* c = (const float4*)(codebook + k * ND);
            float a0 = 0.f, a1 = 0.f, a2 = 0.f, a3 = 0.f;
#pragma unroll
            for (int i = 0; i < ND / 4; i++) {
                float4 v = c[i];
                a0 = fmaf(sx[4 * i + 0], v.x, a0);
                a1 = fmaf(sx[4 * i + 1], v.y, a1);
                a2 = fmaf(sx[4 * i + 2], v.z, a2);
                a3 = fmaf(sx[4 * i + 3], v.w, a3);
            }
            float s = fmaf(-2.f, (a0 + a1) + (a2 + a3), g_esq[k]);
            if (s < best) { best = s; bi = k; }
        }
        sv[tid] = best;
        si[tid] = bi;
        __syncthreads();
        for (int off = 128; off; off >>= 1) {
            if (tid < off) {
                float ov = sv[tid + off];
                int oi = si[tid + off];
                if (ov < sv[tid] || (ov == sv[tid] && oi < si[tid])) {
                    sv[tid] = ov;
                    si[tid] = oi;
                }
            }
            __syncthreads();
        }
        int bk = si[0];
        if ((mode & 1) && tid == 0) out[n] = (float)bk;
        if ((mode & 2) && tid < ND)
            out[idx_off + (size_t)b * (ND * HW) + tid * HW + hw] =
                codebook[bk * ND + tid];
        __syncthreads();
    }
}

// ---- host launcher ----------------------------------------------------------
extern "C" void kernel_launch(void* const* d_in, const int* in_sizes, int n_in,
                              void* d_out, int out_size) {
    const float* laten    = (const float*)d_in[0];
    const float* codebook = (const float*)d_in[1];
    float* out = (float*)d_out;

    int mode, idx_off;
    if (out_size == N_POINTS + N_QUANT) { mode = 3; idx_off = N_POINTS; }
    else if (out_size == N_QUANT)       { mode = 2; idx_off = 0;        }
    else                                { mode = 1; idx_off = 0;        }

    cudaFuncSetAttribute(gemm_argmin_kernel,
                         cudaFuncAttributeMaxDynamicSharedMemorySize, SM_SIZE);

    build_B_kernel<<<NK * 4 / 256, 256>>>(codebook);
    gemm_argmin_kernel<<<N_POINTS / TM, 256, SM_SIZE>>>(laten, codebook, out,
                                                        mode, idx_off);
    rescan_kernel<<<512, 256>>>(laten, codebook, out, mode, idx_off);
}

// round 16
// speedup vs baseline: 1.7845x; 1.1369x over previous
#include <cuda_runtime.h>
#include <cuda_bf16.h>
#include <cuda_fp16.h>
#include <cstdint>

// ============================================================================
// VQVAE quantization: fp16 mma.sync GEMM + top-2 margin + exact fp32 rescue.
//   laten   : (B=32, D=64, H=32, W=32) fp32
//   codebook: (K=2048, D=64) fp32
// Output (fp32): [ idx (32768) | quant (2097152, channel-first) ]
// Approx distances via fp16 GEMM (score err std ~5e-3); any point whose
// top-2 gap < MARGIN (9 sigma) is re-resolved exactly in fp32.
// ============================================================================

#define NB 32
#define ND 64
#define NH 32
#define NW 32
#define NK 2048
#define HW (NH * NW)                  // 1024
#define N_POINTS (NB * HW)            // 32768
#define N_QUANT  (NB * ND * HW)       // 2097152
#define TM 128                        // points per CTA
#define TI 256                        // codes per pipeline iteration
#define NITER (NK / TI)               // 8
#define ROWB 144                      // smem row: 128B data + 16B pad (9%8==1)
#define BUFB (TI * ROWB)              // 36864 per B buffer (256 rows)
#define MARGIN 0.045f

// smem layout (bytes)
#define SM_A    0                     // 128 * 144 = 18432
#define SM_B    18432                 // 2 * 36864 = 73728
#define SM_ESQ  92160                 // 2048 * 4 = 8192
#define SM_SIZE 100352

// ---- device scratch ---------------------------------------------------------
__device__ __align__(16) __half g_B[NK * ND];   // fp16 codebook, 256 KB
__device__ __align__(16) float g_esq[NK];
__device__ int g_rescan[N_POINTS];
__device__ int g_rcount;

// ---- helpers ----------------------------------------------------------------
__device__ __forceinline__ uint32_t smem_u32(const void* p) {
    uint32_t a;
    asm("{ .reg .u64 t; cvta.to.shared.u64 t, %1; cvt.u32.u64 %0, t; }"
        : "=r"(a) : "l"(p));
    return a;
}
#define CP_ASYNC16(s, g) \
    asm volatile("cp.async.cg.shared.global [%0], [%1], 16;" :: "r"(s), "l"(g))
#define CP_COMMIT() asm volatile("cp.async.commit_group;" ::: "memory")
#define CP_WAIT(n)  asm volatile("cp.async.wait_group %0;" :: "n"(n) : "memory")

#define LDSM_X4(r0, r1, r2, r3, a)                                             \
    asm volatile("ldmatrix.sync.aligned.m8n8.x4.shared.b16 {%0,%1,%2,%3}, [%4];" \
                 : "=r"(r0), "=r"(r1), "=r"(r2), "=r"(r3) : "r"(a))

#define MMA_F16(c, a, b0, b1)                                                  \
    asm volatile("mma.sync.aligned.m16n8k16.row.col.f32.f16.f16.f32 "          \
                 "{%0,%1,%2,%3}, {%4,%5,%6,%7}, {%8,%9}, {%0,%1,%2,%3};"       \
                 : "+f"((c)[0]), "+f"((c)[1]), "+f"((c)[2]), "+f"((c)[3])      \
                 : "r"((a)[0]), "r"((a)[1]), "r"((a)[2]), "r"((a)[3]),         \
                   "r"(b0), "r"(b1))

// branch-free top-2 update (FMNMX chains; single predicate gates index SEL)
#define TOP2_UPDATE(s, col, slot) do {                                         \
    float _m1 = fminf((s), b1v[slot]);                                         \
    b2v[slot] = fminf(b2v[slot], fmaxf((s), b1v[slot]));                       \
    bkv[slot] = ((s) < b1v[slot]) ? (col) : bkv[slot];                         \
    b1v[slot] = _m1;                                                           \
} while (0)

// ---- kernel: build fp16 B + exact esq (+ zero rescan counter) ---------------
__global__ void __launch_bounds__(256)
build_B_kernel(const float* __restrict__ codebook) {
    int q = blockIdx.x * 256 + threadIdx.x;
    if (q == 0) g_rcount = 0;
    int k = q >> 2, part = q & 3;
    if (k >= NK) return;
    const float4* src = (const float4*)(codebook + k * ND + part * 16);
    __half2 h2[8];
    float s = 0.f;
#pragma unroll
    for (int i = 0; i < 4; i++) {
        float4 v = src[i];
        s += v.x * v.x + v.y * v.y + v.z * v.z + v.w * v.w;
        h2[2 * i + 0] = __floats2half2_rn(v.x, v.y);
        h2[2 * i + 1] = __floats2half2_rn(v.z, v.w);
    }
    s += __shfl_xor_sync(0xffffffffu, s, 1);
    s += __shfl_xor_sync(0xffffffffu, s, 2);
    uint4* dst = (uint4*)(g_B + (size_t)k * ND + part * 16);
    dst[0] = *(uint4*)&h2[0];
    dst[1] = *(uint4*)&h2[4];
    if (part == 0) g_esq[k] = s;
}

// load one 256-code iteration buffer (2048 x 16B chunks, 8 per thread)
__device__ __forceinline__ void load_iter(uint32_t sb, int buf, int it, int tid) {
    const char* gsrc = (const char*)(g_B + (size_t)it * TI * ND);
    uint32_t dst = sb + SM_B + buf * BUFB;
#pragma unroll
    for (int i = tid; i < TI * 8; i += 256) {
        int row = i >> 3, c = i & 7;
        CP_ASYNC16(dst + row * ROWB + c * 16, gsrc + row * 128 + c * 16);
    }
    CP_COMMIT();
}

// ---- main kernel: A-convert + fp16 GEMM + top-2 argmin + fused finalize ----
__global__ void __launch_bounds__(256, 2)
gemm_argmin_kernel(const float* __restrict__ laten,
                   const float* __restrict__ codebook,
                   float* __restrict__ out, int mode, int idx_off) {
    extern __shared__ char smem[];
    const uint32_t sb = smem_u32(smem);
    const int tid  = threadIdx.x;
    const int lane = tid & 31;
    const int wid  = tid >> 5;
    const int warp_m = (wid & 3) * 32;   // 4 m-warps
    const int warp_n = (wid >> 2) * 32;  // 2 n-warps (cols within 64-code sub-tile)

    const int n0  = blockIdx.x * TM;
    const int b   = n0 >> 10;
    const int hw0 = n0 & (HW - 1);

    // -- prologue: buffer 0 (iteration 0) --
    load_iter(sb, 0, 0, tid);

    // -- A convert: laten -> fp16 rows in smem --
    {
        const int p  = tid & 127;
        const int db = tid >> 7;
        const float* lp = laten + (size_t)b * (ND * HW) + hw0 + p;
#pragma unroll
        for (int i = 0; i < 32; i++) {
            int d = 2 * i + db;
            *(unsigned short*)(smem + SM_A + p * ROWB + d * 2) =
                __half_as_ushort(__float2half_rn(lp[d * HW]));
        }
    }
    // -- esq -> smem --
#pragma unroll
    for (int i = tid; i < NK / 4; i += 256)
        ((float4*)(smem + SM_ESQ))[i] = ((const float4*)g_esq)[i];

    __syncthreads();   // A stage + esq visible

    // ldmatrix lane base addresses
    const uint32_t a_base = sb + SM_A
        + (uint32_t)(warp_m + ((lane >> 3) & 1) * 8 + (lane & 7)) * ROWB
        + (uint32_t)(lane >> 4) * 16;
    const uint32_t b_lane = (uint32_t)(warp_n + (lane >> 4) * 8 + (lane & 7)) * ROWB
        + (uint32_t)((lane >> 3) & 1) * 16;

    // -- hoist A fragments for the whole loop (invariant) --
    uint32_t axh[4][2][4];
#pragma unroll
    for (int ks = 0; ks < 4; ks++) {
#pragma unroll
        for (int mi = 0; mi < 2; mi++)
            LDSM_X4(axh[ks][mi][0], axh[ks][mi][1], axh[ks][mi][2],
                    axh[ks][mi][3], a_base + mi * 16 * ROWB + ks * 32);
    }

    // top-2 state: 4 row-slots (mi*2 + rowhalf)
    float b1v[4] = {3.4e38f, 3.4e38f, 3.4e38f, 3.4e38f};
    float b2v[4] = {3.4e38f, 3.4e38f, 3.4e38f, 3.4e38f};
    int   bkv[4] = {0, 0, 0, 0};

#pragma unroll 1
    for (int it = 0; it < NITER; it++) {
        CP_WAIT(0);        // only pending group: buffer it%2's fill
        __syncthreads();   // buffer it%2 ready for ALL; buffer (it+1)%2 fully
                           // consumed by ALL threads (during iter it-1)

        // prefetch next iteration into the just-freed buffer — full-iteration
        // slack before its CP_WAIT at the top of iter it+1.
        if (it + 1 < NITER) load_iter(sb, (it + 1) & 1, it + 1, tid);

        const uint32_t bufB = sb + SM_B + (it & 1) * BUFB + b_lane;

        // four 64-code sub-tiles
#pragma unroll
        for (int sub = 0; sub < 4; sub++) {
            const uint32_t bB = bufB + sub * (64 * ROWB);
            float acc[2][4][4];
#pragma unroll
            for (int mi = 0; mi < 2; mi++)
#pragma unroll
                for (int ni = 0; ni < 4; ni++)
#pragma unroll
                    for (int q = 0; q < 4; q++) acc[mi][ni][q] = 0.f;

#pragma unroll
            for (int ks = 0; ks < 4; ks++) {
                uint32_t bh0[4], bh1[4];
                LDSM_X4(bh0[0], bh0[1], bh0[2], bh0[3], bB + ks * 32);
                LDSM_X4(bh1[0], bh1[1], bh1[2], bh1[3], bB + 16 * ROWB + ks * 32);
                MMA_F16(acc[0][0], axh[ks][0], bh0[0], bh0[1]);
                MMA_F16(acc[0][1], axh[ks][0], bh0[2], bh0[3]);
                MMA_F16(acc[0][2], axh[ks][0], bh1[0], bh1[1]);
                MMA_F16(acc[0][3], axh[ks][0], bh1[2], bh1[3]);
                MMA_F16(acc[1][0], axh[ks][1], bh0[0], bh0[1]);
                MMA_F16(acc[1][1], axh[ks][1], bh0[2], bh0[3]);
                MMA_F16(acc[1][2], axh[ks][1], bh1[0], bh1[1]);
                MMA_F16(acc[1][3], axh[ks][1], bh1[2], bh1[3]);
            }

            // epilogue: score = esq - 2*dot, branch-free top-2 per row-slot
            const int kb0 = it * TI + sub * 64 + warp_n;
            const float* es = (const float*)(smem + SM_ESQ) + kb0;
#pragma unroll
            for (int ni = 0; ni < 4; ni++) {
                int cb = ni * 8 + 2 * (lane & 3);
                float2 ev = *(const float2*)(es + cb);
                int colg = kb0 + cb;
#pragma unroll
                for (int mi = 0; mi < 2; mi++)
#pragma unroll
                    for (int h = 0; h < 2; h++) {
                        int slot = mi * 2 + h;
                        float s0 = fmaf(-2.f, acc[mi][ni][2 * h + 0], ev.x);
                        float s1 = fmaf(-2.f, acc[mi][ni][2 * h + 1], ev.y);
                        TOP2_UPDATE(s0, colg, slot);
                        TOP2_UPDATE(s1, colg + 1, slot);
                    }
            }
        }
    }
    __syncthreads();

    // -- merge 1: across the 4 lanes sharing each accumulator row ------------
#pragma unroll
    for (int slot = 0; slot < 4; slot++) {
#pragma unroll
        for (int m = 1; m <= 2; m <<= 1) {
            float o1 = __shfl_xor_sync(0xffffffffu, b1v[slot], m);
            float o2 = __shfl_xor_sync(0xffffffffu, b2v[slot], m);
            int   ok = __shfl_xor_sync(0xffffffffu, bkv[slot], m);
            float nb2 = fminf(fmaxf(b1v[slot], o1), fminf(b2v[slot], o2));
            if (o1 < b1v[slot]) { b1v[slot] = o1; bkv[slot] = ok; }
            b2v[slot] = nb2;
        }
    }

    // -- merge 2: across the two n-warp groups; B smem is dead now -----------
    float* cmb = (float*)(smem + SM_B);   // [TM][4]
    if (warp_n == 32 && (lane & 3) == 0) {
#pragma unroll
        for (int slot = 0; slot < 4; slot++) {
            int mi = slot >> 1, h = slot & 1;
            int row = warp_m + mi * 16 + h * 8 + (lane >> 2);
            cmb[row * 4 + 0] = b1v[slot];
            cmb[row * 4 + 1] = b2v[slot];
            ((int*)cmb)[row * 4 + 2] = bkv[slot];
        }
    }
    __syncthreads();
    if (warp_n == 0 && (lane & 3) == 0) {
#pragma unroll
        for (int slot = 0; slot < 4; slot++) {
            int mi = slot >> 1, h = slot & 1;
            int row = warp_m + mi * 16 + h * 8 + (lane >> 2);
            float o1 = cmb[row * 4 + 0];
            float o2 = cmb[row * 4 + 1];
            int   ok = ((int*)cmb)[row * 4 + 2];
            float m2 = fminf(fmaxf(b1v[slot], o1), fminf(b2v[slot], o2));
            int   mk = (b1v[slot] <= o1) ? bkv[slot] : ok;
            float m1 = fminf(b1v[slot], o1);
            cmb[row * 4 + 0] = m1;
            cmb[row * 4 + 1] = m2;
            ((int*)cmb)[row * 4 + 2] = mk;
        }
    }
    __syncthreads();

    // -- fused finalize: 128 threads, one point each --------------------------
    if (tid < TM) {
        float b1 = cmb[tid * 4 + 0];
        float b2 = cmb[tid * 4 + 1];
        int   bk = ((int*)cmb)[tid * 4 + 2];
        int n = n0 + tid;
        bool resc = (b2 - b1 < MARGIN);
        unsigned msk = __ballot_sync(0xffffffffu, resc);
        if (resc) {
            int ldr = __ffs(msk) - 1;
            int base = 0;
            if (lane == ldr) base = atomicAdd(&g_rcount, __popc(msk));
            base = __shfl_sync(msk, base, ldr);
            g_rescan[base + __popc(msk & ((1u << lane) - 1u))] = n;
        } else {
            if (mode & 1) out[n] = (float)bk;
            if (mode & 2) {
                int hw = n & (HW - 1);
                float* oq = out + idx_off + (size_t)b * (ND * HW) + hw;
                const float* cb = codebook + bk * ND;
#pragma unroll
                for (int d = 0; d < ND; d++) oq[d * HW] = __ldg(&cb[d]);
            }
        }
    }
}

// ---- exact fp32 rescan for near-ties ---------------------------------------
__global__ void __launch_bounds__(256)
rescan_kernel(const float* __restrict__ laten, const float* __restrict__ codebook,
              float* __restrict__ out, int mode, int idx_off) {
    __shared__ float sx[ND];
    __shared__ float sv[256];
    __shared__ int si[256];
    int tid = threadIdx.x;
    int cnt = g_rcount;
    for (int ii = blockIdx.x; ii < cnt; ii += gridDim.x) {
        int n = g_rescan[ii];
        int b = n >> 10, hw = n & (HW - 1);
        if (tid < ND) sx[tid] = laten[(size_t)b * (ND * HW) + tid * HW + hw];
        __syncthreads();
        float best = 3.4e38f;
        int bi = 0;
        for (int k = tid; k < NK; k += 256) {
            const float4* c = (const float4*)(codebook + k * ND);
            float a0 = 0.f, a1 = 0.f, a2 = 0.f, a3 = 0.f;
#pragma unroll
            for (int i = 0; i < ND / 4; i++) {
                float4 v = c[i];
                a0 = fmaf(sx[4 * i + 0], v.x, a0);
                a1 = fmaf(sx[4 * i + 1], v.y, a1);
                a2 = fmaf(sx[4 * i + 2], v.z, a2);
                a3 = fmaf(sx[4 * i + 3], v.w, a3);
            }
            float s = fmaf(-2.f, (a0 + a1) + (a2 + a3), g_esq[k]);
            if (s < best) { best = s; bi = k; }
        }
        sv[tid] = best;
        si[tid] = bi;
        __syncthreads();
        for (int off = 128; off; off >>= 1) {
            if (tid < off) {
                float ov = sv[tid + off];
                int oi = si[tid + off];
                if (ov < sv[tid] || (ov == sv[tid] && oi < si[tid])) {
                    sv[tid] = ov;
                    si[tid] = oi;
                }
            }
            __syncthreads();
        }
        int bk = si[0];
        if ((mode & 1) && tid == 0) out[n] = (float)bk;
        if ((mode & 2) && tid < ND)
            out[idx_off + (size_t)b * (ND * HW) + tid * HW + hw] =
                codebook[bk * ND + tid];
        __syncthreads();
    }
}

// ---- host launcher ----------------------------------------------------------
extern "C" void kernel_launch(void* const* d_in, const int* in_sizes, int n_in,
                              void* d_out, int out_size) {
    const float* laten    = (const float*)d_in[0];
    const float* codebook = (const float*)d_in[1];
    float* out = (float*)d_out;

    int mode, idx_off;
    if (out_size == N_POINTS + N_QUANT) { mode = 3; idx_off = N_POINTS; }
    else if (out_size == N_QUANT)       { mode = 2; idx_off = 0;        }
    else                                { mode = 1; idx_off = 0;        }

    cudaFuncSetAttribute(gemm_argmin_kernel,
                         cudaFuncAttributeMaxDynamicSharedMemorySize, SM_SIZE);

    build_B_kernel<<<NK * 4 / 256, 256>>>(codebook);
    gemm_argmin_kernel<<<N_POINTS / TM, 256, SM_SIZE>>>(laten, codebook, out,
                                                        mode, idx_off);
    rescan_kernel<<<512, 256>>>(laten, codebook, out, mode, idx_off);
}